// round 12
// baseline (speedup 1.0000x reference)
#include <cuda_runtime.h>
#include <cstdint>

// C = tril(tril(A) @ tril(B)), N=4096, fp32.
// TF32 m16n8k8 mma.sync; 256x128 block tiles, 64x64 warp tiles (8 warps).
// cp.async 4-stage pipeline. Load balance: tiles with >64 K-chunks are split
// into two independent 128-row half-tiles (disjoint outputs, no scratch).
// Segments launched in ~descending-cost order (greedy ~ LPT).
// TF32 truncation bias cancelled by epilogue scale 1.00071.

#define NN 4096
#define BM 256
#define BN 128
#define BK 32
#define STAGES 4
#define BROW 544
#define A_STAGE (BM * BK * 4)
#define B_STAGE (BK * BROW)
#define STAGE_BYTES (A_STAGE + B_STAGE)
#define B_OFF A_STAGE
#define SMEM_TOTAL (STAGES * STAGE_BYTES)   // 200704
#define TOTAL_SEGS 344                       // 200 unsplit + 72 tiles x 2 halves
#define N_ZERO 240
#define GRID (TOTAL_SEGS + N_ZERO)           // 584
#define BIAS 1.00071f

extern __shared__ char smem[];

template <int V> struct IC { static constexpr int value = V; };

__device__ __forceinline__ uint32_t smem_u32(const void* p) {
    uint32_t a;
    asm("{ .reg .u64 t; cvta.to.shared.u64 t, %1; cvt.u32.u64 %0, t; }" : "=r"(a) : "l"(p));
    return a;
}
__device__ __forceinline__ void cp16(uint32_t dst, const void* src) {
    asm volatile("cp.async.cg.shared.global [%0], [%1], 16;" :: "r"(dst), "l"(src) : "memory");
}
__device__ __forceinline__ uint32_t lds32(uint32_t a) {
    uint32_t v;
    asm volatile("ld.shared.b32 %0, [%1];" : "=r"(v) : "r"(a));
    return v;
}
__device__ __forceinline__ void sts32(uint32_t a, uint32_t v) {
    asm volatile("st.shared.b32 [%0], %1;" :: "r"(a), "r"(v) : "memory");
}
__device__ __forceinline__ void mma8(float* d, const uint32_t* a, const uint32_t* b) {
    asm volatile(
        "mma.sync.aligned.m16n8k8.row.col.f32.tf32.tf32.f32 "
        "{%0,%1,%2,%3}, {%4,%5,%6,%7}, {%8,%9}, {%0,%1,%2,%3};"
        : "+f"(d[0]), "+f"(d[1]), "+f"(d[2]), "+f"(d[3])
        : "r"(a[0]), "r"(a[1]), "r"(a[2]), "r"(a[3]), "r"(b[0]), "r"(b[1]));
}

// tiles with full nCh = v (v multiple of 4): count = 17 - (v+7)/8, bi_min = (v+7)/8 - 1
__device__ __forceinline__ int nTiles(int v) { return 17 - (v + 7) / 8; }
__device__ __forceinline__ int biMin(int v)  { return (v + 7) / 8 - 1; }

__global__ __launch_bounds__(256, 1)
void trilmm6(const float* __restrict__ A,
             const float* __restrict__ B,
             float* __restrict__ C) {
    const int id = blockIdx.x;
    const int tid = threadIdx.x;

    if (id >= TOTAL_SEGS) {
        // strictly-upper 256x128 tile: zero-fill, exit
        int uid = id - TOTAL_SEGS;
        int b2 = 0;
        #pragma unroll 1
        while (uid >= 30 - 2 * b2) { uid -= 30 - 2 * b2; b2++; }
        const int iB = b2 * BM, jB = (2 * b2 + 2 + uid) * BN;
        const float4 z = make_float4(0.f, 0.f, 0.f, 0.f);
        #pragma unroll 4
        for (int it = 0; it < 32; it++) {
            int idx = it * 256 + tid;
            int r = idx >> 5;
            int c = (idx & 31) << 2;
            *reinterpret_cast<float4*>(&C[(iB + r) * NN + jB + c]) = z;
        }
        return;
    }

    // ---- decode id -> (bi, bj, rowLo, half?) in ~descending-cost order ----
    int bi = 0, bj = 0, rowLo = 0;
    bool half = false;
    {
        int rem = id;
        #pragma unroll 1
        for (int sz = 64; sz >= 4; sz -= 2) {
            const int w = 2 * sz;                              // split-tile full nCh
            const int cs = (w > 64 && w <= 128) ? 2 * nTiles(w) : 0;
            const int cu = ((sz & 3) == 0) ? nTiles(sz) : 0;
            if (rem < cs) {
                int ti = rem >> 1, s = rem & 1;
                bi = biMin(w) + ti;
                bj = 2 * (bi + 1) - w / 4;
                half = true;
                rowLo = s ? 0 : 128;      // bottom half first (more chunks)
                break;
            }
            rem -= cs;
            if (rem < cu) {
                bi = biMin(sz) + rem;
                bj = 2 * (bi + 1) - sz / 4;
                break;
            }
            rem -= cu;
        }
    }

    const int jBase = bj * BN;
    const int rowBase = bi * BM + rowLo;       // first output row of this segment
    const int wid = tid >> 5;
    const int lane = tid & 31;
    const int g  = lane >> 2;
    const int kt = lane & 3;

    int mbase, nbase;
    if (!half) { mbase = (wid & 3) * 64; nbase = (wid >> 2) * 64; }
    else       { mbase = (wid & 1) * 64; nbase = (wid >> 1) * 32; }

    const uint32_t sbase = smem_u32(smem);
    const uint32_t xg = (uint32_t)g << 4;

    uint32_t rowrel[4];
    #pragma unroll
    for (int mt = 0; mt < 4; mt++) rowrel[mt] = (uint32_t)(mbase + mt * 16 + g) * 128u;

    auto run = [&](auto ntc) {
        constexpr int NTN  = decltype(ntc)::value;   // 8 (full) or 4 (half)
        constexpr int ROWS = NTN * 32;               // 256 or 128

        uint32_t brel[NTN];
        #pragma unroll
        for (int nt = 0; nt < NTN; nt++) brel[nt] = (uint32_t)(nbase + nt * 8 + g) * 4u;

        float acc[4][NTN][4];
        #pragma unroll
        for (int mt = 0; mt < 4; mt++)
            #pragma unroll
            for (int nt = 0; nt < NTN; nt++)
                #pragma unroll
                for (int f = 0; f < 4; f++)
                    acc[mt][nt][f] = 0.f;

        const int nCh = (rowBase + ROWS - jBase) / BK;

        auto issue = [&](int c) {
            if (c < nCh) {
                const int k0 = jBase + c * BK;
                const uint32_t sb = sbase + (uint32_t)(c % STAGES) * STAGE_BYTES;
                #pragma unroll
                for (int it = 0; it < ROWS / 32; it++) {    // A: ROWS x 128B
                    int idx = it * 256 + tid;
                    int r = idx >> 3, g8 = idx & 7;
                    const float* src = &A[(rowBase + r) * NN + k0 + g8 * 4];
                    uint32_t kb = (uint32_t)(g8 * 16);
                    cp16(sb + (uint32_t)r * 128u + (kb ^ ((uint32_t)(r & 7) << 4)), src);
                }
                #pragma unroll
                for (int it = 0; it < 4; it++) {            // B: 32 rows x 512B
                    int idx = it * 256 + tid;
                    int kk = idx >> 5, n16 = idx & 31;
                    const float* src = &B[(k0 + kk) * NN + jBase + n16 * 4];
                    cp16(sb + B_OFF + (uint32_t)kk * BROW + (uint32_t)n16 * 16u, src);
                }
            }
            asm volatile("cp.async.commit_group;" ::: "memory");
        };

        issue(0); issue(1); issue(2);

        for (int c = 0; c < nCh; c++) {
            asm volatile("cp.async.wait_group 2;" ::: "memory");
            __syncthreads();

            issue(c + 3);

            const int k0 = jBase + c * BK;
            const uint32_t sA = sbase + (uint32_t)(c % STAGES) * STAGE_BYTES;
            const uint32_t sB = sA + B_OFF;

            const bool aEdge = (k0 >= rowBase);
            const bool bEdge = (k0 < jBase + BN);
            if (aEdge) {
                const int off = k0 - rowBase;       // zero A[r][kk] iff kk > r - off
                #pragma unroll 4
                for (int it = 0; it < ROWS / 8; it++) {
                    int idx = it * 256 + tid;
                    int r = idx >> 5, kk = idx & 31;
                    if (kk > r - off)
                        sts32(sA + (uint32_t)r * 128u +
                              (((uint32_t)kk * 4u) ^ ((uint32_t)(r & 7) << 4)), 0u);
                }
            }
            if (bEdge) {
                const int offb = k0 - jBase;        // zero B[kk][n] iff n > offb + kk
                #pragma unroll 4
                for (int it = 0; it < 16; it++) {
                    int idx = it * 256 + tid;
                    int n = idx & 127, kk = idx >> 7;
                    if (n > offb + kk)
                        sts32(sB + (uint32_t)kk * BROW + (uint32_t)n * 4u, 0u);
                }
            }
            if (aEdge || bEdge) __syncthreads();

            #pragma unroll
            for (int ks = 0; ks < 4; ks++) {
                const uint32_t kb0 = (uint32_t)(ks * 32 + kt * 4);
                uint32_t af[4][4];
                #pragma unroll
                for (int mt = 0; mt < 4; mt++) {
                    uint32_t a0 = sA + rowrel[mt] + (kb0 ^ xg);
                    uint32_t a2 = sA + rowrel[mt] + ((kb0 + 16u) ^ xg);
                    af[mt][0] = lds32(a0);
                    af[mt][1] = lds32(a0 + 1024u);
                    af[mt][2] = lds32(a2);
                    af[mt][3] = lds32(a2 + 1024u);
                }
                uint32_t bf[NTN][2];
                const uint32_t bk0 = (uint32_t)(ks * 8 + kt) * BROW;
                #pragma unroll
                for (int nt = 0; nt < NTN; nt++) {
                    uint32_t b0 = sB + bk0 + brel[nt];
                    bf[nt][0] = lds32(b0);
                    bf[nt][1] = lds32(b0 + 4u * BROW);
                }
                #pragma unroll
                for (int mt = 0; mt < 4; mt++)
                    #pragma unroll
                    for (int nt = 0; nt < NTN; nt++)
                        mma8(acc[mt][nt], af[mt], bf[nt]);
            }
        }

        // ---- epilogue (bias-corrected, tril-masked) ----
        const int tig = lane & 3;
        #pragma unroll
        for (int mt = 0; mt < 4; mt++) {
            #pragma unroll
            for (int nt = 0; nt < NTN; nt++) {
                const int gi0 = rowBase + mbase + mt * 16 + g;
                const int gj0 = jBase + nbase + nt * 8 + tig * 2;
                float2 v0;
                v0.x = (gi0 >= gj0)     ? acc[mt][nt][0] * BIAS : 0.f;
                v0.y = (gi0 >= gj0 + 1) ? acc[mt][nt][1] * BIAS : 0.f;
                *reinterpret_cast<float2*>(&C[gi0 * NN + gj0]) = v0;
                const int gi1 = gi0 + 8;
                float2 v1;
                v1.x = (gi1 >= gj0)     ? acc[mt][nt][2] * BIAS : 0.f;
                v1.y = (gi1 >= gj0 + 1) ? acc[mt][nt][3] * BIAS : 0.f;
                *reinterpret_cast<float2*>(&C[gi1 * NN + gj0]) = v1;
            }
        }
    };

    if (!half) run(IC<8>{});
    else       run(IC<4>{});
}

extern "C" void kernel_launch(void* const* d_in, const int* in_sizes, int n_in,
                              void* d_out, int out_size) {
    const float* A = (const float*)d_in[0];
    const float* B = (const float*)d_in[1];
    float* C = (float*)d_out;
    (void)in_sizes; (void)n_in; (void)out_size;

    cudaFuncSetAttribute(trilmm6, cudaFuncAttributeMaxDynamicSharedMemorySize, SMEM_TOTAL);
    trilmm6<<<GRID, 256, SMEM_TOTAL>>>(A, B, C);
}

// round 13
// speedup vs baseline: 1.3496x; 1.3496x over previous
#include <cuda_runtime.h>
#include <cstdint>

// C = tril(tril(A) @ tril(B)), N=4096, fp32.
// TF32 m16n8k8 mma.sync; 256x128 block tiles, 64x64 warp tiles (8 warps).
// cp.async 4-stage pipeline. Split-K load balance: tiles with >64 chunks split
// into seg0 (first half K -> scratch) + seg1 (second half -> C direct).
// The SECOND segment to finish (per-tile atomic counter) adds scratch into C
// in the same kernel, then resets the counter (state invariant per launch).
// TF32 truncation bias cancelled by epilogue scale 1.00071.

#define NN 4096
#define BM 256
#define BN 128
#define BK 32
#define STAGES 4
#define BROW 544
#define A_STAGE (BM * BK * 4)
#define B_STAGE (BK * BROW)
#define STAGE_BYTES (A_STAGE + B_STAGE)
#define B_OFF A_STAGE
#define SMEM_TOTAL (STAGES * STAGE_BYTES)   // 200704
#define TOTAL_SEGS 344                       // 200 unsplit + 72 tiles x 2 segs
#define N_ZERO 240
#define GRID (TOTAL_SEGS + N_ZERO)           // 584
#define BIAS 1.00071f

__device__ float g_scratch[72 * BM * BN];    // split-tile partials (9.4 MB)
__device__ int   g_ctr[72];                  // zero-init; restored to 0 each launch

extern __shared__ char smem[];

__device__ __forceinline__ uint32_t smem_u32(const void* p) {
    uint32_t a;
    asm("{ .reg .u64 t; cvta.to.shared.u64 t, %1; cvt.u32.u64 %0, t; }" : "=r"(a) : "l"(p));
    return a;
}
__device__ __forceinline__ void cp16(uint32_t dst, const void* src) {
    asm volatile("cp.async.cg.shared.global [%0], [%1], 16;" :: "r"(dst), "l"(src) : "memory");
}
__device__ __forceinline__ uint32_t lds32(uint32_t a) {
    uint32_t v;
    asm volatile("ld.shared.b32 %0, [%1];" : "=r"(v) : "r"(a));
    return v;
}
__device__ __forceinline__ void sts32(uint32_t a, uint32_t v) {
    asm volatile("st.shared.b32 [%0], %1;" :: "r"(a), "r"(v) : "memory");
}
__device__ __forceinline__ void mma8(float* d, const uint32_t* a, const uint32_t* b) {
    asm volatile(
        "mma.sync.aligned.m16n8k8.row.col.f32.tf32.tf32.f32 "
        "{%0,%1,%2,%3}, {%4,%5,%6,%7}, {%8,%9}, {%0,%1,%2,%3};"
        : "+f"(d[0]), "+f"(d[1]), "+f"(d[2]), "+f"(d[3])
        : "r"(a[0]), "r"(a[1]), "r"(a[2]), "r"(a[3]), "r"(b[0]), "r"(b[1]));
}

// tiles with full nCh = v (v multiple of 4): count = 17 - (v+7)/8, bi_min = (v+7)/8 - 1
__device__ __forceinline__ int nTiles(int v) { return 17 - (v + 7) / 8; }
__device__ __forceinline__ int biMin(int v)  { return (v + 7) / 8 - 1; }

__global__ __launch_bounds__(256, 1)
void trilmm7(const float* __restrict__ A,
             const float* __restrict__ B,
             float* __restrict__ C) {
    const int id = blockIdx.x;
    const int tid = threadIdx.x;

    if (id >= TOTAL_SEGS) {
        // strictly-upper 256x128 tile: zero-fill, exit
        int uid = id - TOTAL_SEGS;
        int b2 = 0;
        #pragma unroll 1
        while (uid >= 30 - 2 * b2) { uid -= 30 - 2 * b2; b2++; }
        const int iB = b2 * BM, jB = (2 * b2 + 2 + uid) * BN;
        const float4 z = make_float4(0.f, 0.f, 0.f, 0.f);
        #pragma unroll 4
        for (int it = 0; it < 32; it++) {
            int idx = it * 256 + tid;
            int r = idx >> 5;
            int c = (idx & 31) << 2;
            *reinterpret_cast<float4*>(&C[(iB + r) * NN + jB + c]) = z;
        }
        return;
    }

    // ---- decode segment id -> (bi, bj, chunk range), descending size (~LPT) ----
    int bi = 0, bj = 0, segLo = 0, segHi = 0;
    bool isSplit = false, isSeg0 = false;
    {
        int rem = id;
        #pragma unroll 1
        for (int sz = 64; sz >= 4; sz -= 2) {
            const int w = 2 * sz;                               // split-tile full nCh
            const int cs = (w > 64 && w <= 128) ? 2 * nTiles(w) : 0;
            const int cu = ((sz & 3) == 0) ? nTiles(sz) : 0;
            if (rem < cs) {
                int ti = rem >> 1, s = rem & 1;
                bi = biMin(w) + ti;
                bj = 2 * (bi + 1) - w / 4;
                const int h = w / 2;
                isSplit = true;
                isSeg0 = (s == 0);
                segLo = isSeg0 ? 0 : h;
                segHi = isSeg0 ? h : w;
                break;
            }
            rem -= cs;
            if (rem < cu) {
                bi = biMin(sz) + rem;
                bj = 2 * (bi + 1) - sz / 4;
                segLo = 0; segHi = sz;
                break;
            }
            rem -= cu;
        }
    }

    const int iBase = bi * BM;
    const int jBase = bj * BN;
    const int wid = tid >> 5;
    const int lane = tid & 31;
    const int g  = lane >> 2;
    const int kt = lane & 3;
    const int mbase = (wid & 3) * 64;
    const int nbase = (wid >> 2) * 64;

    const uint32_t sbase = smem_u32(smem);
    const uint32_t xg = (uint32_t)g << 4;

    uint32_t rowrel[4], brel[8];
    #pragma unroll
    for (int mt = 0; mt < 4; mt++) rowrel[mt] = (uint32_t)(mbase + mt * 16 + g) * 128u;
    #pragma unroll
    for (int nt = 0; nt < 8; nt++) brel[nt] = (uint32_t)(nbase + nt * 8 + g) * 4u;

    float acc[4][8][4];
    #pragma unroll
    for (int mt = 0; mt < 4; mt++)
        #pragma unroll
        for (int nt = 0; nt < 8; nt++)
            #pragma unroll
            for (int f = 0; f < 4; f++)
                acc[mt][nt][f] = 0.f;

    const int nCh = segHi - segLo;
    const int k0Base = jBase + segLo * BK;

    auto issue = [&](int c) {
        if (c < nCh) {
            const int k0 = k0Base + c * BK;
            const uint32_t sb = sbase + (uint32_t)(c % STAGES) * STAGE_BYTES;
            #pragma unroll
            for (int it = 0; it < 8; it++) {       // A: 256 rows x 128B
                int idx = it * 256 + tid;
                int r = idx >> 3, g8 = idx & 7;
                const float* src = &A[(iBase + r) * NN + k0 + g8 * 4];
                uint32_t kb = (uint32_t)(g8 * 16);
                cp16(sb + (uint32_t)r * 128u + (kb ^ ((uint32_t)(r & 7) << 4)), src);
            }
            #pragma unroll
            for (int it = 0; it < 4; it++) {       // B: 32 rows x 512B (pad 544)
                int idx = it * 256 + tid;
                int kk = idx >> 5, n16 = idx & 31;
                const float* src = &B[(k0 + kk) * NN + jBase + n16 * 4];
                cp16(sb + B_OFF + (uint32_t)kk * BROW + (uint32_t)n16 * 16u, src);
            }
        }
        asm volatile("cp.async.commit_group;" ::: "memory");
    };

    issue(0); issue(1); issue(2);

    for (int c = 0; c < nCh; c++) {
        asm volatile("cp.async.wait_group 2;" ::: "memory");
        __syncthreads();

        issue(c + 3);

        const int k0 = k0Base + c * BK;
        const uint32_t sA = sbase + (uint32_t)(c % STAGES) * STAGE_BYTES;
        const uint32_t sB = sA + B_OFF;

        const bool aEdge = (k0 >= iBase);
        const bool bEdge = (k0 < jBase + BN);
        if (aEdge) {
            const int off = k0 - iBase;            // zero A[r][kk] iff kk > r - off
            #pragma unroll 4
            for (int it = 0; it < 32; it++) {
                int idx = it * 256 + tid;
                int r = idx >> 5, kk = idx & 31;
                if (kk > r - off)
                    sts32(sA + (uint32_t)r * 128u +
                          (((uint32_t)kk * 4u) ^ ((uint32_t)(r & 7) << 4)), 0u);
            }
        }
        if (bEdge) {
            const int offb = k0 - jBase;           // zero B[kk][n] iff n > offb + kk
            #pragma unroll 4
            for (int it = 0; it < 16; it++) {
                int idx = it * 256 + tid;
                int n = idx & 127, kk = idx >> 7;
                if (n > offb + kk)
                    sts32(sB + (uint32_t)kk * BROW + (uint32_t)n * 4u, 0u);
            }
        }
        if (aEdge || bEdge) __syncthreads();

        #pragma unroll
        for (int ks = 0; ks < 4; ks++) {
            const uint32_t kb0 = (uint32_t)(ks * 32 + kt * 4);
            uint32_t af[4][4];
            #pragma unroll
            for (int mt = 0; mt < 4; mt++) {
                uint32_t a0 = sA + rowrel[mt] + (kb0 ^ xg);
                uint32_t a2 = sA + rowrel[mt] + ((kb0 + 16u) ^ xg);
                af[mt][0] = lds32(a0);
                af[mt][1] = lds32(a0 + 1024u);
                af[mt][2] = lds32(a2);
                af[mt][3] = lds32(a2 + 1024u);
            }
            uint32_t bf[8][2];
            const uint32_t bk0 = (uint32_t)(ks * 8 + kt) * BROW;
            #pragma unroll
            for (int nt = 0; nt < 8; nt++) {
                uint32_t b0 = sB + bk0 + brel[nt];
                bf[nt][0] = lds32(b0);
                bf[nt][1] = lds32(b0 + 4u * BROW);
            }
            #pragma unroll
            for (int mt = 0; mt < 4; mt++)
                #pragma unroll
                for (int nt = 0; nt < 8; nt++)
                    mma8(acc[mt][nt], af[mt], bf[nt]);
        }
    }

    // ---- epilogue (bias-corrected) ----
    const int tig = lane & 3;
    if (!isSplit || !isSeg0) {
        // direct, tril-masked (split tiles are fully below diagonal; mask harmless)
        #pragma unroll
        for (int mt = 0; mt < 4; mt++) {
            #pragma unroll
            for (int nt = 0; nt < 8; nt++) {
                const int gi0 = iBase + mbase + mt * 16 + g;
                const int gj0 = jBase + nbase + nt * 8 + tig * 2;
                float2 v0;
                v0.x = (gi0 >= gj0)     ? acc[mt][nt][0] * BIAS : 0.f;
                v0.y = (gi0 >= gj0 + 1) ? acc[mt][nt][1] * BIAS : 0.f;
                *reinterpret_cast<float2*>(&C[gi0 * NN + gj0]) = v0;
                const int gi1 = gi0 + 8;
                float2 v1;
                v1.x = (gi1 >= gj0)     ? acc[mt][nt][2] * BIAS : 0.f;
                v1.y = (gi1 >= gj0 + 1) ? acc[mt][nt][3] * BIAS : 0.f;
                *reinterpret_cast<float2*>(&C[gi1 * NN + gj0]) = v1;
            }
        }
    } else {
        // seg0 partial -> scratch (tile strictly below diagonal: no mask)
        float* S = &g_scratch[((bi - 8) * (bi - 7) + bj) * (BM * BN)];
        #pragma unroll
        for (int mt = 0; mt < 4; mt++) {
            #pragma unroll
            for (int nt = 0; nt < 8; nt++) {
                const int r0 = mbase + mt * 16 + g;
                const int c0 = nbase + nt * 8 + tig * 2;
                float2 v0 = make_float2(acc[mt][nt][0] * BIAS, acc[mt][nt][1] * BIAS);
                *reinterpret_cast<float2*>(&S[r0 * BN + c0]) = v0;
                float2 v1 = make_float2(acc[mt][nt][2] * BIAS, acc[mt][nt][3] * BIAS);
                *reinterpret_cast<float2*>(&S[(r0 + 8) * BN + c0]) = v1;
            }
        }
    }

    // ---- split-tile combine: second finisher adds scratch into C ----
    if (isSplit) {
        const int sid = (bi - 8) * (bi - 7) + bj;
        __shared__ int s_old;
        __threadfence();                 // publish this segment's writes
        __syncthreads();
        if (tid == 0) s_old = atomicAdd(&g_ctr[sid], 1);
        __syncthreads();
        if (s_old == 1) {                // we are second: peer's writes visible
            __threadfence();
            const float* S = &g_scratch[sid * (BM * BN)];
            #pragma unroll 4
            for (int it = 0; it < 32; it++) {      // 256x128 = 8192 float4
                int idx = it * 256 + tid;
                int r = idx >> 5;
                int c = (idx & 31) << 2;
                float4 s = *reinterpret_cast<const float4*>(&S[r * BN + c]);
                float4* cp = reinterpret_cast<float4*>(&C[(iBase + r) * NN + jBase + c]);
                float4 v = *cp;
                v.x += s.x; v.y += s.y; v.z += s.z; v.w += s.w;
                *cp = v;
            }
            __syncthreads();
            if (tid == 0) g_ctr[sid] = 0;          // restore launch-invariant state
        }
    }
}

extern "C" void kernel_launch(void* const* d_in, const int* in_sizes, int n_in,
                              void* d_out, int out_size) {
    const float* A = (const float*)d_in[0];
    const float* B = (const float*)d_in[1];
    float* C = (float*)d_out;
    (void)in_sizes; (void)n_in; (void)out_size;

    cudaFuncSetAttribute(trilmm7, cudaFuncAttributeMaxDynamicSharedMemorySize, SMEM_TOTAL);
    trilmm7<<<GRID, 256, SMEM_TOTAL>>>(A, B, C);
}